// round 1
// baseline (speedup 1.0000x reference)
#include <cuda_runtime.h>
#include <cstdint>

// Problem constants
#define BB   8
#define TT   200
#define UU   100
#define DD   640
#define JJ   640
#define VV   1024

// Main-kernel tiling
#define TILE_T 16
#define TILE_U 8
#define NT_T   13      // ceil(200/16)
#define NT_U   13      // ceil(100/8)
#define BK     32      // K chunk
#define LDA    136     // 128 + 8 pad (conflict-free)
#define BUF_F  (BK*LDA)        // floats per buffer (4352)
#define SMEM_F (4*BUF_F)       // A0,A1,B0,B1
#define SMEM_BYTES (SMEM_F*4)  // 69632

// Scratch for projected enc/pred (fp32, exact)
__device__ float g_enc [BB*TT*JJ];   // [1600][640]
__device__ float g_pred[BB*UU*JJ];   // [800][640]

// ---------------------------------------------------------------------------
// fp32 projection GEMM:  P[M][640] = X[M][640] @ W[640][640] (+ bias)
// ---------------------------------------------------------------------------
__global__ void __launch_bounds__(256) proj_kernel(
    const float* __restrict__ X, const float* __restrict__ W,
    const float* __restrict__ bias, float* __restrict__ P, int M)
{
    const int N = 640, K = 640;
    __shared__ float Xs[16][68];
    __shared__ float Ws[16][68];
    const int tid = threadIdx.x;
    const int tx = tid & 15, ty = tid >> 4;
    const int row0 = blockIdx.y * 64, col0 = blockIdx.x * 64;

    float acc[4][4];
#pragma unroll
    for (int i = 0; i < 4; i++)
#pragma unroll
        for (int j = 0; j < 4; j++) acc[i][j] = 0.f;

    for (int k0 = 0; k0 < K; k0 += 16) {
        // load X tile (64 rows x 16 k), store transposed Xs[k][m]
        {
            int k = tid & 15, m = tid >> 4;
#pragma unroll
            for (int p = 0; p < 4; p++) {
                int mm = m + p * 16;
                int gr = row0 + mm;
                float v = (gr < M) ? X[gr * K + k0 + k] : 0.f;
                Xs[k][mm] = v;
            }
        }
        // load W tile (16 k x 64 n)
        {
            int n = tid & 63, kk = tid >> 6;
#pragma unroll
            for (int p = 0; p < 4; p++)
                Ws[kk + p * 4][n] = W[(k0 + kk + p * 4) * N + col0 + n];
        }
        __syncthreads();
#pragma unroll
        for (int k = 0; k < 16; k++) {
            float4 av = *(const float4*)&Xs[k][ty * 4];
            float4 bv = *(const float4*)&Ws[k][tx * 4];
            float a4[4] = {av.x, av.y, av.z, av.w};
            float b4[4] = {bv.x, bv.y, bv.z, bv.w};
#pragma unroll
            for (int i = 0; i < 4; i++)
#pragma unroll
                for (int j = 0; j < 4; j++) acc[i][j] += a4[i] * b4[j];
        }
        __syncthreads();
    }

#pragma unroll
    for (int i = 0; i < 4; i++) {
        int gr = row0 + ty * 4 + i;
        if (gr < M) {
            int gc = col0 + tx * 4;
            float4 o;
            if (bias) {
                float4 bv = *(const float4*)&bias[gc];
                o.x = acc[i][0] + bv.x; o.y = acc[i][1] + bv.y;
                o.z = acc[i][2] + bv.z; o.w = acc[i][3] + bv.w;
            } else {
                o.x = acc[i][0]; o.y = acc[i][1];
                o.z = acc[i][2]; o.w = acc[i][3];
            }
            *(float4*)&P[gr * N + gc] = o;
        }
    }
}

// ---------------------------------------------------------------------------
// Fused joint kernel: logits = (tanh(enc[t]+pred[u])) @ W_out + b_out
// tf32 mma.sync m16n8k8, block tile 128 rows (16t x 8u) x 128 cols, K=640
// ---------------------------------------------------------------------------
__device__ __forceinline__ float fast_tanh(float x)
{
    // tanh(x) = (e-1)/(e+1), e = 2^(2x*log2 e). Accurate to ~1e-6.
    float e;
    asm("ex2.approx.f32 %0, %1;" : "=f"(e) : "f"(x * 2.885390081777927f));
    float r;
    asm("rcp.approx.f32 %0, %1;" : "=f"(r) : "f"(e + 1.0f));
    return (e - 1.0f) * r;
}

__device__ __forceinline__ uint32_t f2tf32(float x)
{
    uint32_t r;
    asm("cvt.rna.tf32.f32 %0, %1;" : "=r"(r) : "f"(x));
    return r;
}

__device__ __forceinline__ void mma_tf32(float c[4], const uint32_t a[4], const uint32_t b[2])
{
    asm volatile(
        "mma.sync.aligned.m16n8k8.row.col.f32.tf32.tf32.f32 "
        "{%0,%1,%2,%3}, {%4,%5,%6,%7}, {%8,%9}, {%0,%1,%2,%3};"
        : "+f"(c[0]), "+f"(c[1]), "+f"(c[2]), "+f"(c[3])
        : "r"(a[0]), "r"(a[1]), "r"(a[2]), "r"(a[3]),
          "r"(b[0]), "r"(b[1]));
}

__device__ __forceinline__ void build_tiles(
    int tid, int bb, int t0, int u0, int v0, int k0,
    const float* __restrict__ enc, const float* __restrict__ pred,
    const float* __restrict__ Wout, float* __restrict__ A, float* __restrict__ Bt)
{
    // A tile: 128 rows x 32 k, stored As[k][m] (tf32-rounded bits)
#pragma unroll 4
    for (int idx = tid; idx < 128 * BK; idx += 256) {
        int m = idx & 127, k = idx >> 7;
        int t = t0 + (m >> 3), u = u0 + (m & 7);
        float v = 0.f;
        if (t < TT && u < UU) {
            float e = enc [(bb * TT + t) * JJ + (k0 + k)];
            float p = pred[(bb * UU + u) * JJ + (k0 + k)];
            v = fast_tanh(e + p);
        }
        A[k * LDA + m] = __uint_as_float(f2tf32(v));
    }
    // B tile: 32 k x 128 n, stored Bs[k][n]
#pragma unroll
    for (int i = 0; i < 4; i++) {
        int idx = tid + i * 256;
        int n4 = idx & 31, k = idx >> 5;
        const float4 w = *(const float4*)&Wout[(k0 + k) * VV + v0 + n4 * 4];
        float4 wt;
        wt.x = __uint_as_float(f2tf32(w.x));
        wt.y = __uint_as_float(f2tf32(w.y));
        wt.z = __uint_as_float(f2tf32(w.z));
        wt.w = __uint_as_float(f2tf32(w.w));
        *(float4*)&Bt[k * LDA + n4 * 4] = wt;
    }
}

__global__ void __launch_bounds__(256) joint_kernel(
    const float* __restrict__ enc, const float* __restrict__ pred,
    const float* __restrict__ Wout, const float* __restrict__ bout,
    float* __restrict__ out)
{
    extern __shared__ float sm[];
    float* As = sm;                 // 2 buffers * BUF_F
    float* Bs = sm + 2 * BUF_F;     // 2 buffers * BUF_F

    const int tid  = threadIdx.x;
    const int lane = tid & 31, wid = tid >> 5;
    const int warp_m = wid >> 2, warp_n = wid & 3;   // 2 x 4 warp grid
    const int tig = lane & 3, grp = lane >> 2;

    const int v0 = blockIdx.x * 128;
    int by = blockIdx.y;
    const int bb  = by / (NT_T * NT_U);
    int rem = by % (NT_T * NT_U);
    const int t0 = (rem / NT_U) * TILE_T;
    const int u0 = (rem % NT_U) * TILE_U;

    float acc[4][4][4];
#pragma unroll
    for (int i = 0; i < 4; i++)
#pragma unroll
        for (int j = 0; j < 4; j++)
#pragma unroll
            for (int q = 0; q < 4; q++) acc[i][j][q] = 0.f;

    build_tiles(tid, bb, t0, u0, v0, 0, enc, pred, Wout, As, Bs);
    __syncthreads();

    const int NCHUNK = JJ / BK;   // 20
    for (int c = 0; c < NCHUNK; c++) {
        int cur = c & 1;
        if (c + 1 < NCHUNK)
            build_tiles(tid, bb, t0, u0, v0, (c + 1) * BK, enc, pred, Wout,
                        As + (cur ^ 1) * BUF_F, Bs + (cur ^ 1) * BUF_F);

        const float* A  = As + cur * BUF_F;
        const float* Bt = Bs + cur * BUF_F;
#pragma unroll
        for (int ks = 0; ks < 4; ks++) {
            uint32_t af[4][4], bf[4][2];
#pragma unroll
            for (int mi = 0; mi < 4; mi++) {
                int row = warp_m * 64 + mi * 16 + grp;
                af[mi][0] = __float_as_uint(A[(ks * 8 + tig    ) * LDA + row    ]);
                af[mi][1] = __float_as_uint(A[(ks * 8 + tig    ) * LDA + row + 8]);
                af[mi][2] = __float_as_uint(A[(ks * 8 + tig + 4) * LDA + row    ]);
                af[mi][3] = __float_as_uint(A[(ks * 8 + tig + 4) * LDA + row + 8]);
            }
#pragma unroll
            for (int ni = 0; ni < 4; ni++) {
                int col = warp_n * 32 + ni * 8 + grp;
                bf[ni][0] = __float_as_uint(Bt[(ks * 8 + tig    ) * LDA + col]);
                bf[ni][1] = __float_as_uint(Bt[(ks * 8 + tig + 4) * LDA + col]);
            }
#pragma unroll
            for (int mi = 0; mi < 4; mi++)
#pragma unroll
                for (int ni = 0; ni < 4; ni++)
                    mma_tf32(acc[mi][ni], af[mi], bf[ni]);
        }
        __syncthreads();
    }

    // Epilogue: add bias, store (guard partial t/u tiles)
#pragma unroll
    for (int mi = 0; mi < 4; mi++) {
#pragma unroll
        for (int h = 0; h < 2; h++) {
            int r = warp_m * 64 + mi * 16 + grp + h * 8;
            int t = t0 + (r >> 3), u = u0 + (r & 7);
            if (t < TT && u < UU) {
                unsigned off = (unsigned)((bb * TT + t) * UU + u) * VV + v0;
#pragma unroll
                for (int ni = 0; ni < 4; ni++) {
                    int col = warp_n * 32 + ni * 8 + tig * 2;
                    float2 bv = *(const float2*)&bout[v0 + col];
                    float2 o;
                    o.x = acc[mi][ni][h * 2 + 0] + bv.x;
                    o.y = acc[mi][ni][h * 2 + 1] + bv.y;
                    *(float2*)&out[off + col] = o;
                }
            }
        }
    }
}

// ---------------------------------------------------------------------------
extern "C" void kernel_launch(void* const* d_in, const int* in_sizes, int n_in,
                              void* d_out, int out_size)
{
    const float* enc_out  = (const float*)d_in[0];
    const float* pred_out = (const float*)d_in[1];
    const float* W_enc    = (const float*)d_in[2];
    const float* b_enc    = (const float*)d_in[3];
    const float* W_pred   = (const float*)d_in[4];
    const float* W_out    = (const float*)d_in[5];
    const float* b_out    = (const float*)d_in[6];
    float* out = (float*)d_out;

    float *ge, *gp;
    cudaGetSymbolAddress((void**)&ge, g_enc);
    cudaGetSymbolAddress((void**)&gp, g_pred);

    // prejoint projections (fp32 exact)
    proj_kernel<<<dim3(JJ / 64, (BB * TT) / 64), 256>>>(enc_out, W_enc, b_enc, ge, BB * TT);
    proj_kernel<<<dim3(JJ / 64, (BB * UU + 63) / 64), 256>>>(pred_out, W_pred, nullptr, gp, BB * UU);

    // fused joint + vocab GEMM
    cudaFuncSetAttribute(joint_kernel, cudaFuncAttributeMaxDynamicSharedMemorySize, SMEM_BYTES);
    joint_kernel<<<dim3(VV / 128, BB * NT_T * NT_U), 256, SMEM_BYTES>>>(ge, gp, W_out, b_out, out);
}

// round 3
// speedup vs baseline: 4.0173x; 4.0173x over previous
#include <cuda_runtime.h>
#include <cuda_fp16.h>
#include <cstdint>

#define BB 8
#define TT 200
#define UU 100
#define JJ 640
#define VV 1024
#define MM (BB*TT*UU)          // 160000 output rows

// GEMM tiling
#define TILE_M 128
#define TILE_N 256
#define BK     32
#define NCHUNK (JJ/BK)         // 20
#define LDAH   40              // halves per smem row (80B pitch -> conflict-free ldsm)
#define A_BUF  (TILE_M*LDAH)   // 5120 halves
#define B_BUF  (TILE_N*LDAH)   // 10240 halves
#define SMEM_BYTES ((2*A_BUF + 2*B_BUF)*2)   // 61440

// scratch
__device__ float  g_enc [BB*TT*JJ];
__device__ float  g_pred[BB*UU*JJ];
__device__ __half g_wt  [VV*JJ];                 // W_out^T in fp16: [v][j]
__device__ __half g_act [(size_t)MM*JJ];         // tanh(enc+pred) fp16, 205MB

// ---------------------------------------------------------------------------
// helpers
// ---------------------------------------------------------------------------
__device__ __forceinline__ uint32_t smem_u32(const void* p) {
    uint32_t a;
    asm("{ .reg .u64 t; cvta.to.shared.u64 t, %1; cvt.u32.u64 %0, t; }" : "=r"(a) : "l"(p));
    return a;
}
__device__ __forceinline__ float fast_tanh(float x) {
    float e, r;
    asm("ex2.approx.f32 %0, %1;" : "=f"(e) : "f"(x * 2.885390081777927f));
    asm("rcp.approx.f32 %0, %1;" : "=f"(r) : "f"(e + 1.0f));
    return (e - 1.0f) * r;
}
__device__ __forceinline__ void cp16(uint32_t s, const void* g) {
    asm volatile("cp.async.cg.shared.global [%0], [%1], 16;" :: "r"(s), "l"(g));
}
__device__ __forceinline__ void cp_commit() {
    asm volatile("cp.async.commit_group;" ::: "memory");
}
__device__ __forceinline__ void cp_wait0() {
    asm volatile("cp.async.wait_group 0;" ::: "memory");
}
__device__ __forceinline__ void ldsm4(uint32_t* r, const __half* p) {
    uint32_t a = smem_u32(p);
    asm volatile("ldmatrix.sync.aligned.m8n8.x4.shared.b16 {%0,%1,%2,%3}, [%4];"
                 : "=r"(r[0]), "=r"(r[1]), "=r"(r[2]), "=r"(r[3]) : "r"(a));
}
__device__ __forceinline__ void mma16816(float* c, const uint32_t* a, const uint32_t* b) {
    asm volatile(
        "mma.sync.aligned.m16n8k16.row.col.f32.f16.f16.f32 "
        "{%0,%1,%2,%3}, {%4,%5,%6,%7}, {%8,%9}, {%0,%1,%2,%3};"
        : "+f"(c[0]), "+f"(c[1]), "+f"(c[2]), "+f"(c[3])
        : "r"(a[0]), "r"(a[1]), "r"(a[2]), "r"(a[3]), "r"(b[0]), "r"(b[1]));
}

// ---------------------------------------------------------------------------
// prejoint fp32 projections
// ---------------------------------------------------------------------------
__global__ void __launch_bounds__(256) proj_kernel(
    const float* __restrict__ X, const float* __restrict__ W,
    const float* __restrict__ bias, float* __restrict__ P, int M)
{
    const int N = 640, K = 640;
    __shared__ float Xs[16][68];
    __shared__ float Ws[16][68];
    const int tid = threadIdx.x;
    const int tx = tid & 15, ty = tid >> 4;
    const int row0 = blockIdx.y * 64, col0 = blockIdx.x * 64;

    float acc[4][4];
#pragma unroll
    for (int i = 0; i < 4; i++)
#pragma unroll
        for (int j = 0; j < 4; j++) acc[i][j] = 0.f;

    for (int k0 = 0; k0 < K; k0 += 16) {
        {
            int k = tid & 15, m = tid >> 4;
#pragma unroll
            for (int p = 0; p < 4; p++) {
                int mm = m + p * 16;
                int gr = row0 + mm;
                Xs[k][mm] = (gr < M) ? X[gr * K + k0 + k] : 0.f;
            }
        }
        {
            int n = tid & 63, kk = tid >> 6;
#pragma unroll
            for (int p = 0; p < 4; p++)
                Ws[kk + p * 4][n] = W[(k0 + kk + p * 4) * N + col0 + n];
        }
        __syncthreads();
#pragma unroll
        for (int k = 0; k < 16; k++) {
            float4 av = *(const float4*)&Xs[k][ty * 4];
            float4 bv = *(const float4*)&Ws[k][tx * 4];
            float a4[4] = {av.x, av.y, av.z, av.w};
            float b4[4] = {bv.x, bv.y, bv.z, bv.w};
#pragma unroll
            for (int i = 0; i < 4; i++)
#pragma unroll
                for (int j = 0; j < 4; j++) acc[i][j] += a4[i] * b4[j];
        }
        __syncthreads();
    }
#pragma unroll
    for (int i = 0; i < 4; i++) {
        int gr = row0 + ty * 4 + i;
        if (gr < M) {
            int gc = col0 + tx * 4;
            float4 o;
            if (bias) {
                float4 bv = *(const float4*)&bias[gc];
                o.x = acc[i][0] + bv.x; o.y = acc[i][1] + bv.y;
                o.z = acc[i][2] + bv.z; o.w = acc[i][3] + bv.w;
            } else {
                o.x = acc[i][0]; o.y = acc[i][1];
                o.z = acc[i][2]; o.w = acc[i][3];
            }
            *(float4*)&P[gr * N + gc] = o;
        }
    }
}

// ---------------------------------------------------------------------------
// W_out transpose -> fp16: Wt[v][j] = h(W_out[j][v])
// ---------------------------------------------------------------------------
__global__ void __launch_bounds__(256) wt_kernel(const float* __restrict__ W,
                                                 __half* __restrict__ Wt)
{
    __shared__ float tile[32][33];
    int v0 = blockIdx.x * 32, j0 = blockIdx.y * 32;
    int tx = threadIdx.x & 31, ty = threadIdx.x >> 5;
#pragma unroll
    for (int i = 0; i < 4; i++)
        tile[ty + i * 8][tx] = W[(j0 + ty + i * 8) * VV + v0 + tx];
    __syncthreads();
#pragma unroll
    for (int i = 0; i < 4; i++)
        Wt[(size_t)(v0 + ty + i * 8) * JJ + j0 + tx] = __float2half_rn(tile[tx][ty + i * 8]);
}

// ---------------------------------------------------------------------------
// act kernel: act[row][j] = fp16(tanh(enc[bt][j] + pred[bu][j])), row=(bt)*U+u
// ---------------------------------------------------------------------------
__global__ void __launch_bounds__(256) act_kernel(
    const float* __restrict__ enc, const float* __restrict__ pred,
    __half* __restrict__ act)
{
    int idx = blockIdx.x * 256 + threadIdx.x;      // one 8-element group
    int row = idx / 80;
    int jc  = (idx % 80) * 8;
    int bt  = row / UU;
    int b   = row / (TT * UU);
    int u   = row % UU;

    const float4* ep = (const float4*)&enc [(size_t)bt * JJ + jc];
    const float4* pp = (const float4*)&pred[(size_t)(b * UU + u) * JJ + jc];
    float4 e0 = ep[0], e1 = ep[1];
    float4 p0 = pp[0], p1 = pp[1];

    __half2 h[4];
    h[0] = __floats2half2_rn(fast_tanh(e0.x + p0.x), fast_tanh(e0.y + p0.y));
    h[1] = __floats2half2_rn(fast_tanh(e0.z + p0.z), fast_tanh(e0.w + p0.w));
    h[2] = __floats2half2_rn(fast_tanh(e1.x + p1.x), fast_tanh(e1.y + p1.y));
    h[3] = __floats2half2_rn(fast_tanh(e1.z + p1.z), fast_tanh(e1.w + p1.w));
    *(uint4*)&act[(size_t)row * JJ + jc] = *(uint4*)h;
}

// ---------------------------------------------------------------------------
// main GEMM: out[160000][1024] = act[160000][640] @ Wt^T + b_out
// 512 thr, tile 128x256, BK=32, cp.async double buffer, mma m16n8k16 fp16
// ---------------------------------------------------------------------------
__global__ void __launch_bounds__(512, 1) gemm_kernel(
    const __half* __restrict__ A, const __half* __restrict__ Bt,
    const float* __restrict__ bias, float* __restrict__ out)
{
    extern __shared__ __half sm[];
    __half* Asm0 = sm;
    __half* Asm1 = sm + A_BUF;
    __half* Bsm0 = sm + 2 * A_BUF;
    __half* Bsm1 = sm + 2 * A_BUF + B_BUF;

    const int tid  = threadIdx.x;
    const int lane = tid & 31, wid = tid >> 5;
    const int warp_m = wid >> 2, warp_n = wid & 3;     // 4x4 warp grid
    const size_t m0 = (size_t)blockIdx.y * TILE_M;
    const int n0 = blockIdx.x * TILE_N;

    // cp.async load indices
    const int ar  = tid >> 2, ac4 = tid & 3;           // A: row 0..127, 16B chunk 0..3
    const uint32_t a_dst0 = smem_u32(Asm0) + (uint32_t)(ar * LDAH + ac4 * 8) * 2;
    const uint32_t a_dst1 = smem_u32(Asm1) + (uint32_t)(ar * LDAH + ac4 * 8) * 2;
    const __half* a_src = A + (m0 + ar) * JJ + ac4 * 8;
    const uint32_t b_dst0 = smem_u32(Bsm0) + (uint32_t)(ar * LDAH + ac4 * 8) * 2;
    const uint32_t b_dst1 = smem_u32(Bsm1) + (uint32_t)(ar * LDAH + ac4 * 8) * 2;
    const __half* b_src = Bt + (size_t)(n0 + ar) * JJ + ac4 * 8;
    const uint32_t brow2 = (uint32_t)(128 * LDAH) * 2;
    const size_t bsrc2 = (size_t)128 * JJ;

    float acc[2][8][4];
#pragma unroll
    for (int i = 0; i < 2; i++)
#pragma unroll
        for (int j = 0; j < 8; j++)
#pragma unroll
            for (int q = 0; q < 4; q++) acc[i][j][q] = 0.f;

    // prologue: chunk 0 -> buffer 0
    cp16(a_dst0, a_src);
    cp16(b_dst0, b_src);
    cp16(b_dst0 + brow2, b_src + bsrc2);
    cp_commit();

    // ldsm lane decode
    const int g = lane >> 3, lr = lane & 7;
    const int a_row_off = lr + ((g & 1) << 3);         // row within m16
    const int a_col_off = (g >> 1) << 3;               // k half-block
    const int b_row_off = lr + ((g >> 1) << 3);        // n within n16 (2 groups)
    const int b_col_off = (g & 1) << 3;                // k half-block

    for (int c = 0; c < NCHUNK; c++) {
        cp_wait0();
        __syncthreads();

        if (c + 1 < NCHUNK) {
            const int koff = (c + 1) * BK;
            if ((c + 1) & 1) {
                cp16(a_dst1, a_src + koff);
                cp16(b_dst1, b_src + koff);
                cp16(b_dst1 + brow2, b_src + bsrc2 + koff);
            } else {
                cp16(a_dst0, a_src + koff);
                cp16(b_dst0, b_src + koff);
                cp16(b_dst0 + brow2, b_src + bsrc2 + koff);
            }
            cp_commit();
        }

        const __half* As = (c & 1) ? Asm1 : Asm0;
        const __half* Bs = (c & 1) ? Bsm1 : Bsm0;

#pragma unroll
        for (int ks = 0; ks < 2; ks++) {
            uint32_t afr[2][4];
#pragma unroll
            for (int mi = 0; mi < 2; mi++) {
                int row = warp_m * 32 + mi * 16 + a_row_off;
                ldsm4(afr[mi], &As[row * LDAH + ks * 16 + a_col_off]);
            }
            uint32_t bfr[8][2];
#pragma unroll
            for (int j = 0; j < 4; j++) {
                int nrow = warp_n * 64 + j * 16 + b_row_off;
                uint32_t r4[4];
                ldsm4(r4, &Bs[nrow * LDAH + ks * 16 + b_col_off]);
                bfr[2 * j][0] = r4[0]; bfr[2 * j][1] = r4[1];
                bfr[2 * j + 1][0] = r4[2]; bfr[2 * j + 1][1] = r4[3];
            }
#pragma unroll
            for (int mi = 0; mi < 2; mi++)
#pragma unroll
                for (int nj = 0; nj < 8; nj++)
                    mma16816(acc[mi][nj], afr[mi], bfr[nj]);
        }
        __syncthreads();
    }

    // epilogue: bias + store (fully coalescable 32B segments)
    const int qr = lane >> 2, qc = (lane & 3) * 2;
    const int colbase = n0 + warp_n * 64;
#pragma unroll
    for (int mi = 0; mi < 2; mi++) {
        size_t row = m0 + warp_m * 32 + mi * 16 + qr;
        float* o0 = out + row * VV + colbase;
        float* o1 = o0 + (size_t)8 * VV;
#pragma unroll
        for (int nj = 0; nj < 8; nj++) {
            int col = nj * 8 + qc;
            float2 bv = *(const float2*)&bias[colbase + col];
            float2 w0 = { acc[mi][nj][0] + bv.x, acc[mi][nj][1] + bv.y };
            float2 w1 = { acc[mi][nj][2] + bv.x, acc[mi][nj][3] + bv.y };
            *(float2*)(o0 + col) = w0;
            *(float2*)(o1 + col) = w1;
        }
    }
}

// ---------------------------------------------------------------------------
extern "C" void kernel_launch(void* const* d_in, const int* in_sizes, int n_in,
                              void* d_out, int out_size)
{
    const float* enc_out  = (const float*)d_in[0];
    const float* pred_out = (const float*)d_in[1];
    const float* W_enc    = (const float*)d_in[2];
    const float* b_enc    = (const float*)d_in[3];
    const float* W_pred   = (const float*)d_in[4];
    const float* W_out    = (const float*)d_in[5];
    const float* b_out    = (const float*)d_in[6];
    float* out = (float*)d_out;

    float *ge, *gp; __half *gw, *ga;
    cudaGetSymbolAddress((void**)&ge, g_enc);
    cudaGetSymbolAddress((void**)&gp, g_pred);
    cudaGetSymbolAddress((void**)&gw, g_wt);
    cudaGetSymbolAddress((void**)&ga, g_act);

    proj_kernel<<<dim3(JJ / 64, (BB * TT) / 64), 256>>>(enc_out, W_enc, b_enc, ge, BB * TT);
    proj_kernel<<<dim3(JJ / 64, (BB * UU + 63) / 64), 256>>>(pred_out, W_pred, nullptr, gp, BB * UU);
    wt_kernel<<<dim3(VV / 32, JJ / 32), 256>>>(W_out, gw);
    act_kernel<<<(MM * 80) / 256, 256>>>(ge, gp, ga);

    cudaFuncSetAttribute(gemm_kernel, cudaFuncAttributeMaxDynamicSharedMemorySize, SMEM_BYTES);
    gemm_kernel<<<dim3(VV / TILE_N, MM / TILE_M), 512, SMEM_BYTES>>>(ga, gw, b_out, out);
}